// round 9
// baseline (speedup 1.0000x reference)
#include <cuda_runtime.h>
#include <cuda_fp16.h>

// SlinkyForcePredictor — fused per-edge kernel, v8 (= v7 + alignment fix).
// v7 crashed: W1 landed at smem offset 131272 (8 mod 16) after Wg->GG swap,
// making the float4 staging store misaligned (STS.128 trap). alignas(16) fixes.
// Structure: gate matvec folded into stage3 via precomputed (Wsc0@Wg),(Wl2_0@Wg);
// pairwise-h stage1b; register-resident last layer.
// X phys layout: [x1,x2,x3,x8, x4,x5,x6,x7, x0,a0,a1,a2]; HID overlay 10/11.

#define MULC 50
#define NBC 10
#define HIDC 100
#define TE 32
#define NTHREADS 512

typedef unsigned long long u64;

__device__ __half GGg[3][MULC][MULC][2];   // [layer][u][v][{x0w, a0w}]

struct SM {
  float X[TE][MULC][12];
  float s[TE][MULC];
  float shv[TE][12];
  float emb[TE][12];
  __half Wsc[3][MULC][MULC];
  __half Wl1[MULC][MULC];
  __half Wl2[3][MULC][MULC];
  alignas(16) __half GG[MULC][MULC][2];
  alignas(16) float W1[NBC][HIDC];
  float b1[104];
  alignas(16) __half W2i[50][152][2];     // [h/2][c][h&1]
};

__device__ __forceinline__ float geluf(float x) {
  float x3 = x * x * x;
  float t = tanhf(0.7978845608028654f * (x + 0.044715f * x3));
  return 0.5f * x * (1.0f + t);
}
__device__ __forceinline__ float sigmoidf(float x) { return 1.0f / (1.0f + expf(-x)); }
__device__ __forceinline__ float siluf(float x) { return x * sigmoidf(x); }

__device__ __forceinline__ float2 ldh2(const __half* p) {
  return __half22float2(*reinterpret_cast<const __half2*>(p));
}
__device__ __forceinline__ u64 pk(float lo, float hi) {
  u64 r; asm("mov.b64 %0, {%1, %2};" : "=l"(r) : "f"(lo), "f"(hi)); return r;
}
__device__ __forceinline__ void upk(float& lo, float& hi, u64 v) {
  asm("mov.b64 {%0, %1}, %2;" : "=f"(lo), "=f"(hi) : "l"(v));
}
__device__ __forceinline__ void fma2(u64& d, u64 a, u64 b) {
  asm("fma.rn.f32x2 %0, %1, %2, %3;" : "=l"(d) : "l"(a), "l"(b), "l"(d));
}

// ---------------- pre-kernel: GG = fused gate weights ----------------
__global__ void gg_kernel(const float* __restrict__ Wsc_g,
                          const float* __restrict__ Wlin2_g,
                          const float* __restrict__ Wgate_g)
{
  const int u = blockIdx.x;      // 0..49
  const int i = blockIdx.y;      // layer 0..2
  const int v = threadIdx.x;     // 0..63
  if (v >= MULC) return;
  const float* A = Wsc_g + i * 7500 + u * 50;    // Wsc0[u][*]
  const float* B = Wlin2_g + i * 7500 + u * 50;  // Wl2_0[u][*]
  const float* G = Wgate_g + i * 2500;           // Wg[t][v]
  float sx = 0.0f, sa = 0.0f;
  #pragma unroll 10
  for (int t = 0; t < MULC; t++) {
    float gv = G[t * 50 + v];
    sx = fmaf(A[t], gv, sx);
    sa = fmaf(B[t], gv, sa);
  }
  const float K1 = 0.9238795325112867f * 0.1414213562373095f;   // cs/sqrt(50)
  const float K0 = 0.3826834323650898f * 0.05773502691896258f;  // cx/sqrt(300)
  GGg[i][u][v][0] = __float2half_rn(K1 * sx);
  GGg[i][u][v][1] = __float2half_rn(K0 * sa);
}

// ---------------- main kernel ----------------
__global__ __launch_bounds__(NTHREADS, 1)
void slinky_kernel(const float* __restrict__ node_pos,
                   const float* __restrict__ bar_alpha,
                   const float* __restrict__ W_embed,
                   const float* __restrict__ Wsc_g,
                   const float* __restrict__ Wlin1_g,
                   const float* __restrict__ W1_g,
                   const float* __restrict__ b1_g,
                   const float* __restrict__ W2_g,
                   const float* __restrict__ Wlin2_g,
                   const float* __restrict__ Wout_g,
                   float* __restrict__ out)
{
  extern __shared__ __align__(16) float smem_raw[];
  SM* sm = reinterpret_cast<SM*>(smem_raw);

  const int tid = threadIdx.x;
  const int w   = tid >> 5;
  const int ln  = tid & 31;
  const int e0  = 2 * w;
  const int e1  = 2 * w + 1;
  const bool act = (ln < 25);
  const int u0 = 2 * ln;

  const float INVS50 = 0.1414213562373095f;
  const float CS = 0.9238795325112867f;
  const float CX = 0.3826834323650898f;
  const float K1 = CS * INVS50;
  const float CXK0 = CX * 0.05773502691896258f;
  const float CXK1 = CX * 0.02357022603955159f;
  const float CXK2 = CX * 0.01825741858350554f;

  // ---------------- preprocess ----------------
  {
    const int half = ln >> 4;
    const int l16 = ln & 15;
    const int le = e0 + half;
    const int eg = blockIdx.x * TE + le;
    const float* p6 = node_pos + (size_t)eg * 6;
    float ex = p6[1] - p6[0];
    float ey = p6[3] - p6[2];
    float ez = p6[5] - p6[4];
    float r = sqrtf(ex * ex + ey * ey + ez * ez);
    float inv = 1.0f / fmaxf(r, 1e-12f);
    float vx = ex * inv, vy = ey * inv, vz = ez * inv;
    if (l16 == 0) {
      const float s3 = 1.7320508075688772f;
      const float s5 = 2.23606797749979f;
      const float s15 = 3.872983346207417f;
      float* shp = sm->shv[le];
      shp[0] = 1.0f;
      shp[1] = s3 * vx;
      shp[2] = s3 * vy;
      shp[3] = s3 * vz;
      shp[4] = s15 * vx * vz;
      shp[5] = s15 * vx * vy;
      shp[6] = s5 * (vy * vy - 0.5f * (vx * vx + vz * vz));
      shp[7] = s15 * vy * vz;
      shp[8] = 0.5f * s15 * (vz * vz - vx * vx);
    }
    if (l16 < NBC) {
      const float step = 4.0f / 11.0f;
      float c = (float)(l16 + 1) * step;
      float diff = (r - c) / step;
      float up = diff + 1.0f, um = 1.0f - diff;
      float ua = (up > 0.0f) ? expf(-1.0f / up) : 0.0f;
      float ub = (um > 0.0f) ? expf(-1.0f / um) : 0.0f;
      sm->emb[le][l16] = (1.14136f * 7.3890560989306495f * 3.1622776601683795f) * ua * ub;
    }
  }
  if (act) {
    const int geb = blockIdx.x * TE;
    #pragma unroll
    for (int e = 0; e < 2; e++) {
      int le = e0 + e;
      int eg = geb + le;
      float ba_s = bar_alpha[2 * eg];
      float ba_d = bar_alpha[2 * eg + 1];
      #pragma unroll
      for (int ch = 0; ch < 2; ch++) {
        int u = u0 + ch;
        float we = W_embed[u];
        sm->s[le][u] = ba_s * we;
        float* xr = sm->X[le][u];
        #pragma unroll
        for (int k = 0; k < 8; k++) xr[k] = 0.0f;
        xr[8] = ba_d * we;                       // x0 at phys 8
      }
    }
  }

  float xs[2][2][3];   // last-layer gated l=1 values

  // ---------------- layers ----------------
  for (int i = 0; i < 3; i++) {
    __syncthreads();
    // weight staging
    {
      const float2* g2 = reinterpret_cast<const float2*>(Wsc_g + i * 7500);
      __half2* dh = reinterpret_cast<__half2*>(&sm->Wsc[0][0][0]);
      for (int t = tid; t < 3750; t += NTHREADS) dh[t] = __float22half2_rn(g2[t]);
      g2 = reinterpret_cast<const float2*>(Wlin1_g + i * 7500);
      dh = reinterpret_cast<__half2*>(&sm->Wl1[0][0]);
      for (int t = tid; t < 1250; t += NTHREADS) dh[t] = __float22half2_rn(g2[t]);
      g2 = reinterpret_cast<const float2*>(Wlin2_g + i * 7500);
      dh = reinterpret_cast<__half2*>(&sm->Wl2[0][0][0]);
      for (int t = tid; t < 3750; t += NTHREADS) dh[t] = __float22half2_rn(g2[t]);
      const unsigned* gg = reinterpret_cast<const unsigned*>(&GGg[i][0][0][0]);
      unsigned* dg = reinterpret_cast<unsigned*>(&sm->GG[0][0][0]);
      for (int t = tid; t < 2500; t += NTHREADS) dg[t] = gg[t];
      const float4* g4 = reinterpret_cast<const float4*>(W1_g + i * 1000);
      float4* d4 = reinterpret_cast<float4*>(&sm->W1[0][0]);
      for (int t = tid; t < 250; t += NTHREADS) d4[t] = g4[t];
      if (tid < 100) sm->b1[tid] = b1_g[i * 100 + tid];
      const float* g = W2_g + i * 75000;
      for (int t = tid; t < 15000; t += NTHREADS) {
        int h = t / 150;
        int c = t - h * 150;
        int u = c / 3;
        int p = c - u * 3;
        sm->W2i[h >> 1][c][h & 1] = __float2half_rn(g[h * 750 + u * 15 + p]);
      }
    }
    __syncthreads();

    // ---- stage 1a: radial MLP hidden -> X slots 10/11 (h pairs) ----
    #pragma unroll
    for (int j = 0; j < 4; j++) {
      int h = ln + 32 * j;
      if (h < HIDC) {
        float a0 = 0.0f, a1 = 0.0f;
        #pragma unroll
        for (int b = 0; b < NBC; b++) {
          float w1 = sm->W1[b][h];
          a0 = fmaf(sm->emb[e0][b], w1, a0);
          a1 = fmaf(sm->emb[e1][b], w1, a1);
        }
        sm->X[e0][h >> 1][10 + (h & 1)] = geluf(a0 * 0.31622776601683794f + sm->b1[h]);
        sm->X[e1][h >> 1][10 + (h & 1)] = geluf(a1 * 0.31622776601683794f + sm->b1[h]);
      }
    }
    __syncwarp();

    // ---- stage 1b: pairwise-h matvec ----
    u64 AC0[6] = {}, AC1[6] = {};
    if (act) {
      #pragma unroll 2
      for (int h2 = 0; h2 < 50; h2++) {
        u64 H0 = *reinterpret_cast<const u64*>(&sm->X[e0][h2][10]);
        u64 H1 = *reinterpret_cast<const u64*>(&sm->X[e1][h2][10]);
        const __half* wp = &sm->W2i[h2][6 * ln][0];
        #pragma unroll
        for (int j = 0; j < 6; j++) {
          float2 wj = ldh2(wp + 2 * j);
          u64 W = pk(wj.x, wj.y);
          fma2(AC0[j], H0, W);
          fma2(AC1[j], H1, W);
        }
      }
    }
    float wv[2][2][3];
    #pragma unroll
    for (int j = 0; j < 6; j++) {
      float lo, hi;
      upk(lo, hi, AC0[j]); wv[0][j / 3][j % 3] = lo + hi;
      upk(lo, hi, AC1[j]); wv[1][j / 3][j % 3] = lo + hi;
    }

    // ---- stage 2: source matvecs (packed over ch) ----
    u64 H0p = 0ull, H1p = 0ull, SC0p = 0ull, SC1p = 0ull;
    if (act) {
      #pragma unroll 5
      for (int t = 0; t < MULC; t++) {
        float s0 = sm->s[e0][t];
        float s1 = sm->s[e1][t];
        float2 wl = ldh2(&sm->Wl1[t][u0]);
        float2 ws = ldh2(&sm->Wsc[0][t][u0]);
        u64 WL = pk(wl.x, wl.y), WS = pk(ws.x, ws.y);
        u64 S0 = pk(s0, s0), S1 = pk(s1, s1);
        fma2(H0p, S0, WL);
        fma2(SC0p, S0, WS);
        fma2(H1p, S1, WL);
        fma2(SC1p, S1, WS);
      }
    }
    float h0a[2][2], sca[2][2];
    upk(h0a[0][0], h0a[0][1], H0p);
    upk(h0a[1][0], h0a[1][1], H1p);
    upk(sca[0][0], sca[0][1], SC0p);
    upk(sca[1][0], sca[1][1], SC1p);
    __syncwarp();
    if (act) {
      #pragma unroll
      for (int e = 0; e < 2; e++) {
        int le = e0 + e;
        #pragma unroll
        for (int ch = 0; ch < 2; ch++) {
          int u = u0 + ch;
          float h0 = h0a[e][ch] * INVS50;
          float* xr = sm->X[le][u];
          xr[9]  = h0 * wv[e][ch][0] * 0.1f;   // a0
          xr[10] = h0 * wv[e][ch][1] * 0.1f;   // a1
          xr[11] = h0 * wv[e][ch][2] * 0.1f;   // a2
          sm->s[le][u] = siluf(CS * sca[e][ch] * INVS50);
        }
      }
    }
    __syncwarp();

    // ---- stage 3 (+folded gate): pairs (x1,x2)(x3,x8)(x4,x5)(x6,x7)(x0,a0)(a1,a2) ----
    u64 A[2][2][6] = {};
    u64 GA[2][2] = {};
    if (act) {
      #pragma unroll 1
      for (int u = 0; u < MULC; u++) {
        float2 ws0 = ldh2(&sm->Wsc[0][u][u0]);
        float2 ws1 = ldh2(&sm->Wsc[1][u][u0]);
        float2 ws2 = ldh2(&sm->Wsc[2][u][u0]);
        float2 l0 = ldh2(&sm->Wl2[0][u][u0]);
        float2 l1 = ldh2(&sm->Wl2[1][u][u0]);
        float2 l2 = ldh2(&sm->Wl2[2][u][u0]);
        uint2 ggw = *reinterpret_cast<const uint2*>(&sm->GG[u][u0][0]);
        float2 gg0 = __half22float2(*reinterpret_cast<const __half2*>(&ggw.x));
        float2 gg1 = __half22float2(*reinterpret_cast<const __half2*>(&ggw.y));
        u64 GGx = pk(gg0.x, gg0.y);
        u64 GGy = pk(gg1.x, gg1.y);
        u64 Q0x = pk(ws1.x, ws1.x);
        u64 Q1x = pk(ws1.x, ws2.x);
        u64 Q2x = pk(ws2.x, ws2.x);
        u64 Q3x = pk(ws0.x, l0.x);
        u64 Q4x = pk(l1.x, l2.x);
        u64 Q0y = pk(ws1.y, ws1.y);
        u64 Q1y = pk(ws1.y, ws2.y);
        u64 Q2y = pk(ws2.y, ws2.y);
        u64 Q3y = pk(ws0.y, l0.y);
        u64 Q4y = pk(l1.y, l2.y);
        {
          const ulonglong2* xp = reinterpret_cast<const ulonglong2*>(sm->X[e0][u]);
          ulonglong2 xa = xp[0], xb = xp[1], xc = xp[2];
          fma2(A[0][0][0], xa.x, Q0x);
          fma2(A[0][0][1], xa.y, Q1x);
          fma2(A[0][0][2], xb.x, Q2x);
          fma2(A[0][0][3], xb.y, Q2x);
          fma2(A[0][0][4], xc.x, Q3x);
          fma2(A[0][0][5], xc.y, Q4x);
          fma2(GA[0][0],   xc.x, GGx);
          fma2(A[0][1][0], xa.x, Q0y);
          fma2(A[0][1][1], xa.y, Q1y);
          fma2(A[0][1][2], xb.x, Q2y);
          fma2(A[0][1][3], xb.y, Q2y);
          fma2(A[0][1][4], xc.x, Q3y);
          fma2(A[0][1][5], xc.y, Q4y);
          fma2(GA[0][1],   xc.x, GGy);
        }
        {
          const ulonglong2* xp = reinterpret_cast<const ulonglong2*>(sm->X[e1][u]);
          ulonglong2 xa = xp[0], xb = xp[1], xc = xp[2];
          fma2(A[1][0][0], xa.x, Q0x);
          fma2(A[1][0][1], xa.y, Q1x);
          fma2(A[1][0][2], xb.x, Q2x);
          fma2(A[1][0][3], xb.y, Q2x);
          fma2(A[1][0][4], xc.x, Q3x);
          fma2(A[1][0][5], xc.y, Q4x);
          fma2(GA[1][0],   xc.x, GGx);
          fma2(A[1][1][0], xa.x, Q0y);
          fma2(A[1][1][1], xa.y, Q1y);
          fma2(A[1][1][2], xb.x, Q2y);
          fma2(A[1][1][3], xb.y, Q2y);
          fma2(A[1][1][4], xc.x, Q3y);
          fma2(A[1][1][5], xc.y, Q4y);
          fma2(GA[1][1],   xc.x, GGy);
        }
      }
    }
    __syncwarp();   // all lanes done reading X
    if (act) {
      #pragma unroll
      for (int e = 0; e < 2; e++) {
        int le = e0 + e;
        const float* shl = sm->shv[le];
        #pragma unroll
        for (int ch = 0; ch < 2; ch++) {
          int u = u0 + ch;
          float ac1, ac2, ac3, ac8, ac4, ac5, ac6, ac7, ac0, b0, b1v, b2;
          upk(ac1, ac2, A[e][ch][0]);
          upk(ac3, ac8, A[e][ch][1]);
          upk(ac4, ac5, A[e][ch][2]);
          upk(ac6, ac7, A[e][ch][3]);
          upk(ac0, b0,  A[e][ch][4]);
          upk(b1v, b2,  A[e][ch][5]);
          float glo, ghi;
          upk(glo, ghi, GA[e][ch]);
          float g = sigmoidf((glo + ghi) * INVS50);
          float x0p = K1 * ac0 + CXK0 * b0;
          float y1 = (K1 * ac1 + CXK1 * b1v * shl[1]) * g;
          float y2 = (K1 * ac2 + CXK1 * b1v * shl[2]) * g;
          float y3 = (K1 * ac3 + CXK1 * b1v * shl[3]) * g;
          if (i < 2) {
            float y4 = (K1 * ac4 + CXK2 * b2 * shl[4]) * g;
            float y5 = (K1 * ac5 + CXK2 * b2 * shl[5]) * g;
            float y6 = (K1 * ac6 + CXK2 * b2 * shl[6]) * g;
            float y7 = (K1 * ac7 + CXK2 * b2 * shl[7]) * g;
            float y8 = (K1 * ac8 + CXK2 * b2 * shl[8]) * g;
            float* xr = sm->X[le][u];
            *reinterpret_cast<float4*>(xr)     = make_float4(y1, y2, y3, y8);
            *reinterpret_cast<float4*>(xr + 4) = make_float4(y4, y5, y6, y7);
            xr[8] = siluf(x0p);
          } else {
            xs[e][ch][0] = y1;
            xs[e][ch][1] = y2;
            xs[e][ch][2] = y3;
          }
        }
      }
    }
    __syncwarp();
  }

  // ---------------- output ----------------
  {
    float p[2][3] = {};
    if (act) {
      float wo0 = Wout_g[u0];
      float wo1 = Wout_g[u0 + 1];
      #pragma unroll
      for (int e = 0; e < 2; e++) {
        p[e][0] = xs[e][0][0] * wo0 + xs[e][1][0] * wo1;
        p[e][1] = xs[e][0][1] * wo0 + xs[e][1][1] * wo1;
        p[e][2] = xs[e][0][2] * wo0 + xs[e][1][2] * wo1;
      }
    }
    #pragma unroll
    for (int off = 16; off; off >>= 1) {
      #pragma unroll
      for (int e = 0; e < 2; e++) {
        p[e][0] += __shfl_xor_sync(0xffffffffu, p[e][0], off);
        p[e][1] += __shfl_xor_sync(0xffffffffu, p[e][1], off);
        p[e][2] += __shfl_xor_sync(0xffffffffu, p[e][2], off);
      }
    }
    if (ln == 0) {
      int eg0 = blockIdx.x * TE + e0;
      float* od = out + (size_t)(2 * eg0) * 3;
      od[0] = 0.0f; od[1] = 0.0f; od[2] = 0.0f;
      od[3] = p[0][0] * INVS50;
      od[4] = p[0][1] * INVS50;
      od[5] = p[0][2] * INVS50;
      od[6] = 0.0f; od[7] = 0.0f; od[8] = 0.0f;
      od[9]  = p[1][0] * INVS50;
      od[10] = p[1][1] * INVS50;
      od[11] = p[1][2] * INVS50;
    }
  }
}

extern "C" void kernel_launch(void* const* d_in, const int* in_sizes, int n_in,
                              void* d_out, int out_size) {
  const float* node_pos = (const float*)d_in[0];
  const float* bar_alpha = (const float*)d_in[1];
  const float* W_embed  = (const float*)d_in[2];
  const float* Wsc      = (const float*)d_in[3];
  const float* Wlin1    = (const float*)d_in[4];
  const float* W1       = (const float*)d_in[5];
  const float* b1       = (const float*)d_in[6];
  const float* W2       = (const float*)d_in[7];
  const float* Wlin2    = (const float*)d_in[8];
  const float* Wgate    = (const float*)d_in[9];
  const float* W_out    = (const float*)d_in[10];
  float* out = (float*)d_out;

  gg_kernel<<<dim3(MULC, 3), 64>>>(Wsc, Wlin2, Wgate);

  int E = in_sizes[0] / 6;
  size_t smem = sizeof(SM);
  cudaFuncSetAttribute(slinky_kernel, cudaFuncAttributeMaxDynamicSharedMemorySize, (int)smem);
  slinky_kernel<<<E / TE, NTHREADS, smem>>>(node_pos, bar_alpha, W_embed, Wsc, Wlin1,
                                            W1, b1, W2, Wlin2, W_out, out);
}

// round 10
// speedup vs baseline: 1.1366x; 1.1366x over previous
#include <cuda_runtime.h>
#include <cuda_fp16.h>

// SlinkyForcePredictor — fused per-edge kernel, v9.
// = v5 (best, 751.5us) + the single isolated win from v8: pairwise-h stage1b.
//   - HID stored as (h_even,h_odd) pairs at X slots 10/11 (8B-aligned, slots
//     reused by a1/a2 after stage1b) -> stage1b uses LDS.64 H-pairs, halving fma2s.
//   - W2 staged interleaved: W2i[h/2][c][h&1], one aligned ldh2 per weight pair.
// Gate fold REVERTED (ALU-heavy, unproven). Stage-3 unroll 2 KEPT (unroll 1 was
// the v6/v8 regressor). X layout as v5: [x1,x2,x3,x0,x4..x7,x8,a0,a1,a2].

#define MULC 50
#define NBC 10
#define HIDC 100
#define TE 32
#define NTHREADS 512

typedef unsigned long long u64;

struct SM {
  float X[TE][MULC][12];      // phys: [x1,x2,x3,x0,x4,x5,x6,x7,x8,a0,a1,a2]
  float s[TE][MULC];
  float shv[TE][12];
  float emb[TE][12];
  __half Wsc[3][MULC][MULC];
  __half Wl1[MULC][MULC];
  __half Wl2[3][MULC][MULC];
  __half Wg[MULC][MULC];
  float W1[NBC][HIDC];
  float b1[104];
  __half W2i[50][152][2];     // [h/2][c][h&1], c = u*3+p
};

__device__ __forceinline__ float geluf(float x) {
  float x3 = x * x * x;
  float t = tanhf(0.7978845608028654f * (x + 0.044715f * x3));
  return 0.5f * x * (1.0f + t);
}
__device__ __forceinline__ float sigmoidf(float x) { return 1.0f / (1.0f + expf(-x)); }
__device__ __forceinline__ float siluf(float x) { return x * sigmoidf(x); }

__device__ __forceinline__ float2 ldh2(const __half* p) {
  return __half22float2(*reinterpret_cast<const __half2*>(p));
}
__device__ __forceinline__ u64 pk(float lo, float hi) {
  u64 r; asm("mov.b64 %0, {%1, %2};" : "=l"(r) : "f"(lo), "f"(hi)); return r;
}
__device__ __forceinline__ void upk(float& lo, float& hi, u64 v) {
  asm("mov.b64 {%0, %1}, %2;" : "=f"(lo), "=f"(hi) : "l"(v));
}
__device__ __forceinline__ void fma2(u64& d, u64 a, u64 b) {
  asm("fma.rn.f32x2 %0, %1, %2, %3;" : "=l"(d) : "l"(a), "l"(b), "l"(d));
}

__global__ __launch_bounds__(NTHREADS, 1)
void slinky_kernel(const float* __restrict__ node_pos,
                   const float* __restrict__ bar_alpha,
                   const float* __restrict__ W_embed,
                   const float* __restrict__ Wsc_g,
                   const float* __restrict__ Wlin1_g,
                   const float* __restrict__ W1_g,
                   const float* __restrict__ b1_g,
                   const float* __restrict__ W2_g,
                   const float* __restrict__ Wlin2_g,
                   const float* __restrict__ Wgate_g,
                   const float* __restrict__ Wout_g,
                   float* __restrict__ out)
{
  extern __shared__ __align__(16) float smem_raw[];
  SM* sm = reinterpret_cast<SM*>(smem_raw);

  const int tid = threadIdx.x;
  const int w   = tid >> 5;
  const int ln  = tid & 31;
  const int e0  = 2 * w;
  const int e1  = 2 * w + 1;
  const bool act = (ln < 25);
  const int u0 = 2 * ln;

  const float INVS50 = 0.1414213562373095f;
  const float CS = 0.9238795325112867f;
  const float CX = 0.3826834323650898f;
  const float CXK0 = CX * 0.05773502691896258f;
  const float CXK1 = CX * 0.02357022603955159f;
  const float CXK2 = CX * 0.01825741858350554f;

  // ---------------- preprocess ----------------
  {
    const int half = ln >> 4;
    const int l16 = ln & 15;
    const int le = e0 + half;
    const int eg = blockIdx.x * TE + le;
    const float* p6 = node_pos + (size_t)eg * 6;
    float ex = p6[1] - p6[0];
    float ey = p6[3] - p6[2];
    float ez = p6[5] - p6[4];
    float r = sqrtf(ex * ex + ey * ey + ez * ez);
    float inv = 1.0f / fmaxf(r, 1e-12f);
    float vx = ex * inv, vy = ey * inv, vz = ez * inv;
    if (l16 == 0) {
      const float s3 = 1.7320508075688772f;
      const float s5 = 2.23606797749979f;
      const float s15 = 3.872983346207417f;
      float* shp = sm->shv[le];
      shp[0] = 1.0f;
      shp[1] = s3 * vx;
      shp[2] = s3 * vy;
      shp[3] = s3 * vz;
      shp[4] = s15 * vx * vz;
      shp[5] = s15 * vx * vy;
      shp[6] = s5 * (vy * vy - 0.5f * (vx * vx + vz * vz));
      shp[7] = s15 * vy * vz;
      shp[8] = 0.5f * s15 * (vz * vz - vx * vx);
    }
    if (l16 < NBC) {
      const float step = 4.0f / 11.0f;
      float c = (float)(l16 + 1) * step;
      float diff = (r - c) / step;
      float up = diff + 1.0f, um = 1.0f - diff;
      float ua = (up > 0.0f) ? expf(-1.0f / up) : 0.0f;
      float ub = (um > 0.0f) ? expf(-1.0f / um) : 0.0f;
      sm->emb[le][l16] = (1.14136f * 7.3890560989306495f * 3.1622776601683795f) * ua * ub;
    }
  }
  if (act) {
    const int geb = blockIdx.x * TE;
    #pragma unroll
    for (int e = 0; e < 2; e++) {
      int le = e0 + e;
      int eg = geb + le;
      float ba_s = bar_alpha[2 * eg];
      float ba_d = bar_alpha[2 * eg + 1];
      #pragma unroll
      for (int ch = 0; ch < 2; ch++) {
        int u = u0 + ch;
        float we = W_embed[u];
        sm->s[le][u] = ba_s * we;
        float* xr = sm->X[le][u];
        xr[0] = 0.0f; xr[1] = 0.0f; xr[2] = 0.0f;
        xr[3] = ba_d * we;                        // x0 at phys 3
        xr[4] = 0.0f; xr[5] = 0.0f; xr[6] = 0.0f; xr[7] = 0.0f; xr[8] = 0.0f;
      }
    }
  }

  // ---------------- layers ----------------
  for (int i = 0; i < 3; i++) {
    __syncthreads();
    // weight staging: fp32 global -> fp16 smem
    {
      const float2* g2 = reinterpret_cast<const float2*>(Wsc_g + i * 7500);
      __half2* dh = reinterpret_cast<__half2*>(&sm->Wsc[0][0][0]);
      for (int t = tid; t < 3750; t += NTHREADS) dh[t] = __float22half2_rn(g2[t]);
      g2 = reinterpret_cast<const float2*>(Wlin1_g + i * 7500);
      dh = reinterpret_cast<__half2*>(&sm->Wl1[0][0]);
      for (int t = tid; t < 1250; t += NTHREADS) dh[t] = __float22half2_rn(g2[t]);
      g2 = reinterpret_cast<const float2*>(Wlin2_g + i * 7500);
      dh = reinterpret_cast<__half2*>(&sm->Wl2[0][0][0]);
      for (int t = tid; t < 3750; t += NTHREADS) dh[t] = __float22half2_rn(g2[t]);
      g2 = reinterpret_cast<const float2*>(Wgate_g + i * 2500);
      dh = reinterpret_cast<__half2*>(&sm->Wg[0][0]);
      for (int t = tid; t < 1250; t += NTHREADS) dh[t] = __float22half2_rn(g2[t]);
      const float4* g4 = reinterpret_cast<const float4*>(W1_g + i * 1000);
      float4* d4 = reinterpret_cast<float4*>(&sm->W1[0][0]);
      for (int t = tid; t < 250; t += NTHREADS) d4[t] = g4[t];
      if (tid < 100) sm->b1[tid] = b1_g[i * 100 + tid];
      const float* g = W2_g + i * 75000;     // (100,750); need cols u*15+p, p<3
      for (int t = tid; t < 15000; t += NTHREADS) {
        int h = t / 150;
        int c = t - h * 150;
        int u = c / 3;
        int p = c - u * 3;
        sm->W2i[h >> 1][c][h & 1] = __float2half_rn(g[h * 750 + u * 15 + p]);
      }
    }
    __syncthreads();

    // ---- stage 1a: radial MLP hidden -> X slots 10/11 (h pairs, 8B-aligned) ----
    #pragma unroll
    for (int j = 0; j < 4; j++) {
      int h = ln + 32 * j;
      if (h < HIDC) {
        float a0 = 0.0f, a1 = 0.0f;
        #pragma unroll
        for (int b = 0; b < NBC; b++) {
          float w1 = sm->W1[b][h];
          a0 = fmaf(sm->emb[e0][b], w1, a0);
          a1 = fmaf(sm->emb[e1][b], w1, a1);
        }
        sm->X[e0][h >> 1][10 + (h & 1)] = geluf(a0 * 0.31622776601683794f + sm->b1[h]);
        sm->X[e1][h >> 1][10 + (h & 1)] = geluf(a1 * 0.31622776601683794f + sm->b1[h]);
      }
    }
    __syncwarp();

    // ---- stage 1b: pairwise-h matvec (f32x2 over h parity) ----
    u64 AC0[6] = {}, AC1[6] = {};
    if (act) {
      #pragma unroll 2
      for (int h2 = 0; h2 < 50; h2++) {
        u64 H0 = *reinterpret_cast<const u64*>(&sm->X[e0][h2][10]);
        u64 H1 = *reinterpret_cast<const u64*>(&sm->X[e1][h2][10]);
        const __half* wp = &sm->W2i[h2][6 * ln][0];
        #pragma unroll
        for (int j = 0; j < 6; j++) {
          float2 wj = ldh2(wp + 2 * j);
          u64 W = pk(wj.x, wj.y);
          fma2(AC0[j], H0, W);
          fma2(AC1[j], H1, W);
        }
      }
    }
    float wv[2][2][3];
    #pragma unroll
    for (int j = 0; j < 6; j++) {
      float lo, hi;
      upk(lo, hi, AC0[j]); wv[0][j / 3][j % 3] = lo + hi;
      upk(lo, hi, AC1[j]); wv[1][j / 3][j % 3] = lo + hi;
    }

    // ---- stage 2: source matvecs (packed over ch) ----
    u64 H0p = 0ull, H1p = 0ull, SC0p = 0ull, SC1p = 0ull;
    if (act) {
      #pragma unroll 5
      for (int t = 0; t < MULC; t++) {
        float s0 = sm->s[e0][t];
        float s1 = sm->s[e1][t];
        float2 wl = ldh2(&sm->Wl1[t][u0]);
        float2 ws = ldh2(&sm->Wsc[0][t][u0]);
        u64 WL = pk(wl.x, wl.y), WS = pk(ws.x, ws.y);
        u64 S0 = pk(s0, s0), S1 = pk(s1, s1);
        fma2(H0p, S0, WL);
        fma2(SC0p, S0, WS);
        fma2(H1p, S1, WL);
        fma2(SC1p, S1, WS);
      }
    }
    float h0a[2][2], sca[2][2];
    upk(h0a[0][0], h0a[0][1], H0p);
    upk(h0a[1][0], h0a[1][1], H1p);
    upk(sca[0][0], sca[0][1], SC0p);
    upk(sca[1][0], sca[1][1], SC1p);
    __syncwarp();
    if (act) {
      #pragma unroll
      for (int e = 0; e < 2; e++) {
        int le = e0 + e;
        #pragma unroll
        for (int ch = 0; ch < 2; ch++) {
          int u = u0 + ch;
          float h0 = h0a[e][ch] * INVS50;
          float* xr = sm->X[le][u];
          xr[9]  = h0 * wv[e][ch][0] * 0.1f;   // a0
          xr[10] = h0 * wv[e][ch][1] * 0.1f;   // a1
          xr[11] = h0 * wv[e][ch][2] * 0.1f;   // a2
          sm->s[le][u] = siluf(CS * sca[e][ch] * INVS50);
        }
      }
    }
    __syncwarp();

    // ---- stage 3: packed f32x2; pairs (x1,x2)(x3,x0)(x4,x5)(x6,x7)(x8,a0)(a1,a2) ----
    u64 A[2][2][6] = {};
    if (act) {
      #pragma unroll 2
      for (int u = 0; u < MULC; u++) {
        float2 ws0 = ldh2(&sm->Wsc[0][u][u0]);
        float2 ws1 = ldh2(&sm->Wsc[1][u][u0]);
        float2 ws2 = ldh2(&sm->Wsc[2][u][u0]);
        float2 l0 = ldh2(&sm->Wl2[0][u][u0]);
        float2 l1 = ldh2(&sm->Wl2[1][u][u0]);
        float2 l2 = ldh2(&sm->Wl2[2][u][u0]);
        u64 Q0x = pk(ws1.x, ws1.x);
        u64 Q1x = pk(ws1.x, ws0.x);
        u64 Q2x = pk(ws2.x, ws2.x);
        u64 Q3x = pk(ws2.x, l0.x);
        u64 Q4x = pk(l1.x, l2.x);
        u64 Q0y = pk(ws1.y, ws1.y);
        u64 Q1y = pk(ws1.y, ws0.y);
        u64 Q2y = pk(ws2.y, ws2.y);
        u64 Q3y = pk(ws2.y, l0.y);
        u64 Q4y = pk(l1.y, l2.y);
        {
          const ulonglong2* xp = reinterpret_cast<const ulonglong2*>(sm->X[e0][u]);
          ulonglong2 xa = xp[0], xb = xp[1], xc = xp[2];
          fma2(A[0][0][0], xa.x, Q0x);
          fma2(A[0][0][1], xa.y, Q1x);
          fma2(A[0][0][2], xb.x, Q2x);
          fma2(A[0][0][3], xb.y, Q2x);
          fma2(A[0][0][4], xc.x, Q3x);
          fma2(A[0][0][5], xc.y, Q4x);
          fma2(A[0][1][0], xa.x, Q0y);
          fma2(A[0][1][1], xa.y, Q1y);
          fma2(A[0][1][2], xb.x, Q2y);
          fma2(A[0][1][3], xb.y, Q2y);
          fma2(A[0][1][4], xc.x, Q3y);
          fma2(A[0][1][5], xc.y, Q4y);
        }
        {
          const ulonglong2* xp = reinterpret_cast<const ulonglong2*>(sm->X[e1][u]);
          ulonglong2 xa = xp[0], xb = xp[1], xc = xp[2];
          fma2(A[1][0][0], xa.x, Q0x);
          fma2(A[1][0][1], xa.y, Q1x);
          fma2(A[1][0][2], xb.x, Q2x);
          fma2(A[1][0][3], xb.y, Q2x);
          fma2(A[1][0][4], xc.x, Q3x);
          fma2(A[1][0][5], xc.y, Q4x);
          fma2(A[1][1][0], xa.x, Q0y);
          fma2(A[1][1][1], xa.y, Q1y);
          fma2(A[1][1][2], xb.x, Q2y);
          fma2(A[1][1][3], xb.y, Q2y);
          fma2(A[1][1][4], xc.x, Q3y);
          fma2(A[1][1][5], xc.y, Q4y);
        }
      }
    }
    __syncwarp();   // all lanes done reading X
    if (act) {
      #pragma unroll
      for (int e = 0; e < 2; e++) {
        int le = e0 + e;
        const float* shl = sm->shv[le];
        #pragma unroll
        for (int ch = 0; ch < 2; ch++) {
          int u = u0 + ch;
          float ac0, ac1, ac2, ac3, ac4, ac5, ac6, ac7, ac8, b0, b1v, b2;
          upk(ac1, ac2, A[e][ch][0]);
          upk(ac3, ac0, A[e][ch][1]);
          upk(ac4, ac5, A[e][ch][2]);
          upk(ac6, ac7, A[e][ch][3]);
          upk(ac8, b0,  A[e][ch][4]);
          upk(b1v, b2,  A[e][ch][5]);
          float* xr = sm->X[le][u];
          xr[3] = CS * INVS50 * ac0 + CXK0 * b0;
          xr[0] = CS * INVS50 * ac1 + CXK1 * b1v * shl[1];
          xr[1] = CS * INVS50 * ac2 + CXK1 * b1v * shl[2];
          xr[2] = CS * INVS50 * ac3 + CXK1 * b1v * shl[3];
          xr[4] = CS * INVS50 * ac4 + CXK2 * b2 * shl[4];
          xr[5] = CS * INVS50 * ac5 + CXK2 * b2 * shl[5];
          xr[6] = CS * INVS50 * ac6 + CXK2 * b2 * shl[6];
          xr[7] = CS * INVS50 * ac7 + CXK2 * b2 * shl[7];
          xr[8] = CS * INVS50 * ac8 + CXK2 * b2 * shl[8];
        }
      }
    }
    __syncwarp();

    // ---- stage 4: gate (packed over ch) ----
    u64 GA0 = 0ull, GA1 = 0ull;
    if (act) {
      #pragma unroll 5
      for (int u = 0; u < MULC; u++) {
        float t0 = sm->X[e0][u][3];   // x0 at phys 3
        float t1 = sm->X[e1][u][3];
        float2 wg = ldh2(&sm->Wg[u][u0]);
        u64 WG = pk(wg.x, wg.y);
        u64 T0 = pk(t0, t0), T1 = pk(t1, t1);
        fma2(GA0, T0, WG);
        fma2(GA1, T1, WG);
      }
    }
    float ga[2][2];
    upk(ga[0][0], ga[0][1], GA0);
    upk(ga[1][0], ga[1][1], GA1);
    __syncwarp();
    if (act) {
      #pragma unroll
      for (int e = 0; e < 2; e++) {
        int le = e0 + e;
        #pragma unroll
        for (int ch = 0; ch < 2; ch++) {
          int u = u0 + ch;
          float g = sigmoidf(ga[e][ch] * INVS50);
          float* xr = sm->X[le][u];
          float4 Af = *reinterpret_cast<const float4*>(xr);
          float4 Bf = *reinterpret_cast<const float4*>(xr + 4);
          float x8 = xr[8];
          float4 qa = make_float4(Af.x * g, Af.y * g, Af.z * g, siluf(Af.w));
          float4 qb = make_float4(Bf.x * g, Bf.y * g, Bf.z * g, Bf.w * g);
          *reinterpret_cast<float4*>(xr)     = qa;
          *reinterpret_cast<float4*>(xr + 4) = qb;
          xr[8] = x8 * g;
        }
      }
    }
    __syncwarp();
  }

  // ---------------- output: x1..x3 at phys 0..2 ----------------
  {
    float p[2][3] = {};
    if (act) {
      float wo0 = Wout_g[u0];
      float wo1 = Wout_g[u0 + 1];
      #pragma unroll
      for (int e = 0; e < 2; e++) {
        int le = e0 + e;
        const float* r0 = sm->X[le][u0];
        const float* r1 = sm->X[le][u0 + 1];
        p[e][0] = r0[0] * wo0 + r1[0] * wo1;
        p[e][1] = r0[1] * wo0 + r1[1] * wo1;
        p[e][2] = r0[2] * wo0 + r1[2] * wo1;
      }
    }
    #pragma unroll
    for (int off = 16; off; off >>= 1) {
      #pragma unroll
      for (int e = 0; e < 2; e++) {
        p[e][0] += __shfl_xor_sync(0xffffffffu, p[e][0], off);
        p[e][1] += __shfl_xor_sync(0xffffffffu, p[e][1], off);
        p[e][2] += __shfl_xor_sync(0xffffffffu, p[e][2], off);
      }
    }
    if (ln == 0) {
      int eg0 = blockIdx.x * TE + e0;
      float* od = out + (size_t)(2 * eg0) * 3;
      od[0] = 0.0f; od[1] = 0.0f; od[2] = 0.0f;
      od[3] = p[0][0] * INVS50;
      od[4] = p[0][1] * INVS50;
      od[5] = p[0][2] * INVS50;
      od[6] = 0.0f; od[7] = 0.0f; od[8] = 0.0f;
      od[9]  = p[1][0] * INVS50;
      od[10] = p[1][1] * INVS50;
      od[11] = p[1][2] * INVS50;
    }
  }
}

extern "C" void kernel_launch(void* const* d_in, const int* in_sizes, int n_in,
                              void* d_out, int out_size) {
  const float* node_pos = (const float*)d_in[0];
  const float* bar_alpha = (const float*)d_in[1];
  const float* W_embed  = (const float*)d_in[2];
  const float* Wsc      = (const float*)d_in[3];
  const float* Wlin1    = (const float*)d_in[4];
  const float* W1       = (const float*)d_in[5];
  const float* b1       = (const float*)d_in[6];
  const float* W2       = (const float*)d_in[7];
  const float* Wlin2    = (const float*)d_in[8];
  const float* Wgate    = (const float*)d_in[9];
  const float* W_out    = (const float*)d_in[10];
  float* out = (float*)d_out;

  int E = in_sizes[0] / 6;
  size_t smem = sizeof(SM);
  cudaFuncSetAttribute(slinky_kernel, cudaFuncAttributeMaxDynamicSharedMemorySize, (int)smem);
  slinky_kernel<<<E / TE, NTHREADS, smem>>>(node_pos, bar_alpha, W_embed, Wsc, Wlin1,
                                            W1, b1, W2, Wlin2, Wgate, W_out, out);
}

// round 11
// speedup vs baseline: 1.3113x; 1.1537x over previous
#include <cuda_runtime.h>
#include <cuda_fp16.h>

// SlinkyForcePredictor — fused per-edge kernel, v10.
// = v9 (best, 749.6us) + (a) one-shot weight repack pre-kernel: main-kernel
//   staging becomes a pure contiguous uint4 copy (was ~49 iter/warp/layer with
//   scattered W2 gather + div/mod chains + fp32->fp16 converts);
//   (b) register-resident last layer: layer 2 writes only x0 to smem, keeps
//   y1..y3 in regs, output computed without the final writeback round-trip.
// X phys layout: [x1,x2,x3,x0,x4,x5,x6,x7,x8,a0,a1,a2]; HID overlay 10/11.

#define MULC 50
#define NBC 10
#define HIDC 100
#define TE 32
#define NTHREADS 512

typedef unsigned long long u64;

struct PW {                    // packed per-layer weights, 74816 B (16-mult)
  __half Wsc[3][MULC][MULC];   // 15000
  __half Wl1[MULC][MULC];      // 5000
  __half Wl2[3][MULC][MULC];   // 15000
  __half Wg[MULC][MULC];       // 5000
  float  W1[NBC][HIDC];        // 4000
  float  b1[104];              // 416
  __half W2i[50][152][2];      // 30400  [h/2][c][h&1], c=u*3+p
};
static_assert(sizeof(PW) % 16 == 0, "PW must be 16B multiple");

__device__ PW PWg[3];

struct SM {
  float X[TE][MULC][12];
  float s[TE][MULC];
  float shv[TE][12];
  float emb[TE][12];
  PW pw;                       // offset 86272 (16-aligned)
};

__device__ __forceinline__ float geluf(float x) {
  float x3 = x * x * x;
  float t = tanhf(0.7978845608028654f * (x + 0.044715f * x3));
  return 0.5f * x * (1.0f + t);
}
__device__ __forceinline__ float sigmoidf(float x) { return 1.0f / (1.0f + expf(-x)); }
__device__ __forceinline__ float siluf(float x) { return x * sigmoidf(x); }

__device__ __forceinline__ float2 ldh2(const __half* p) {
  return __half22float2(*reinterpret_cast<const __half2*>(p));
}
__device__ __forceinline__ u64 pk(float lo, float hi) {
  u64 r; asm("mov.b64 %0, {%1, %2};" : "=l"(r) : "f"(lo), "f"(hi)); return r;
}
__device__ __forceinline__ void upk(float& lo, float& hi, u64 v) {
  asm("mov.b64 {%0, %1}, %2;" : "=f"(lo), "=f"(hi) : "l"(v));
}
__device__ __forceinline__ void fma2(u64& d, u64 a, u64 b) {
  asm("fma.rn.f32x2 %0, %1, %2, %3;" : "=l"(d) : "l"(a), "l"(b), "l"(d));
}

// ---------------- pre-kernel: repack all weights once ----------------
__global__ void pack_kernel(const float* __restrict__ Wsc_g,
                            const float* __restrict__ Wlin1_g,
                            const float* __restrict__ Wlin2_g,
                            const float* __restrict__ Wgate_g,
                            const float* __restrict__ W1_g,
                            const float* __restrict__ b1_g,
                            const float* __restrict__ W2_g)
{
  const int i = blockIdx.x;            // layer
  PW* p = &PWg[i];
  __half* d;
  d = &p->Wsc[0][0][0];
  for (int t = threadIdx.x; t < 7500; t += blockDim.x) d[t] = __float2half_rn(Wsc_g[i * 7500 + t]);
  d = &p->Wl1[0][0];
  for (int t = threadIdx.x; t < 2500; t += blockDim.x) d[t] = __float2half_rn(Wlin1_g[i * 7500 + t]);
  d = &p->Wl2[0][0][0];
  for (int t = threadIdx.x; t < 7500; t += blockDim.x) d[t] = __float2half_rn(Wlin2_g[i * 7500 + t]);
  d = &p->Wg[0][0];
  for (int t = threadIdx.x; t < 2500; t += blockDim.x) d[t] = __float2half_rn(Wgate_g[i * 2500 + t]);
  float* f = &p->W1[0][0];
  for (int t = threadIdx.x; t < 1000; t += blockDim.x) f[t] = W1_g[i * 1000 + t];
  for (int t = threadIdx.x; t < 104; t += blockDim.x) p->b1[t] = (t < 100) ? b1_g[i * 100 + t] : 0.0f;
  const float* g = W2_g + i * 75000;   // (100,750); need cols u*15+p, p<3
  for (int t = threadIdx.x; t < 15000; t += blockDim.x) {
    int h = t / 150;
    int c = t - h * 150;
    int u = c / 3;
    int pp = c - u * 3;
    p->W2i[h >> 1][c][h & 1] = __float2half_rn(g[h * 750 + u * 15 + pp]);
  }
}

// ---------------- main kernel ----------------
__global__ __launch_bounds__(NTHREADS, 1)
void slinky_kernel(const float* __restrict__ node_pos,
                   const float* __restrict__ bar_alpha,
                   const float* __restrict__ W_embed,
                   const float* __restrict__ Wout_g,
                   float* __restrict__ out)
{
  extern __shared__ __align__(16) float smem_raw[];
  SM* sm = reinterpret_cast<SM*>(smem_raw);

  const int tid = threadIdx.x;
  const int w   = tid >> 5;
  const int ln  = tid & 31;
  const int e0  = 2 * w;
  const int e1  = 2 * w + 1;
  const bool act = (ln < 25);
  const int u0 = 2 * ln;

  const float INVS50 = 0.1414213562373095f;
  const float CS = 0.9238795325112867f;
  const float CX = 0.3826834323650898f;
  const float CXK0 = CX * 0.05773502691896258f;
  const float CXK1 = CX * 0.02357022603955159f;
  const float CXK2 = CX * 0.01825741858350554f;

  // ---------------- preprocess ----------------
  {
    const int half = ln >> 4;
    const int l16 = ln & 15;
    const int le = e0 + half;
    const int eg = blockIdx.x * TE + le;
    const float* p6 = node_pos + (size_t)eg * 6;
    float ex = p6[1] - p6[0];
    float ey = p6[3] - p6[2];
    float ez = p6[5] - p6[4];
    float r = sqrtf(ex * ex + ey * ey + ez * ez);
    float inv = 1.0f / fmaxf(r, 1e-12f);
    float vx = ex * inv, vy = ey * inv, vz = ez * inv;
    if (l16 == 0) {
      const float s3 = 1.7320508075688772f;
      const float s5 = 2.23606797749979f;
      const float s15 = 3.872983346207417f;
      float* shp = sm->shv[le];
      shp[0] = 1.0f;
      shp[1] = s3 * vx;
      shp[2] = s3 * vy;
      shp[3] = s3 * vz;
      shp[4] = s15 * vx * vz;
      shp[5] = s15 * vx * vy;
      shp[6] = s5 * (vy * vy - 0.5f * (vx * vx + vz * vz));
      shp[7] = s15 * vy * vz;
      shp[8] = 0.5f * s15 * (vz * vz - vx * vx);
    }
    if (l16 < NBC) {
      const float step = 4.0f / 11.0f;
      float c = (float)(l16 + 1) * step;
      float diff = (r - c) / step;
      float up = diff + 1.0f, um = 1.0f - diff;
      float ua = (up > 0.0f) ? expf(-1.0f / up) : 0.0f;
      float ub = (um > 0.0f) ? expf(-1.0f / um) : 0.0f;
      sm->emb[le][l16] = (1.14136f * 7.3890560989306495f * 3.1622776601683795f) * ua * ub;
    }
  }
  if (act) {
    const int geb = blockIdx.x * TE;
    #pragma unroll
    for (int e = 0; e < 2; e++) {
      int le = e0 + e;
      int eg = geb + le;
      float ba_s = bar_alpha[2 * eg];
      float ba_d = bar_alpha[2 * eg + 1];
      #pragma unroll
      for (int ch = 0; ch < 2; ch++) {
        int u = u0 + ch;
        float we = W_embed[u];
        sm->s[le][u] = ba_s * we;
        float* xr = sm->X[le][u];
        xr[0] = 0.0f; xr[1] = 0.0f; xr[2] = 0.0f;
        xr[3] = ba_d * we;                        // x0 at phys 3
        xr[4] = 0.0f; xr[5] = 0.0f; xr[6] = 0.0f; xr[7] = 0.0f; xr[8] = 0.0f;
      }
    }
  }

  float xs[2][2][3];   // layer-2 l=1 values (pre-gate, then gated in place)

  // ---------------- layers ----------------
  for (int i = 0; i < 3; i++) {
    __syncthreads();
    // weight staging: one contiguous vector copy
    {
      const uint4* src = reinterpret_cast<const uint4*>(&PWg[i]);
      uint4* dst = reinterpret_cast<uint4*>(&sm->pw);
      for (int t = tid; t < (int)(sizeof(PW) / 16); t += NTHREADS) dst[t] = src[t];
    }
    __syncthreads();

    // ---- stage 1a: radial MLP hidden -> X slots 10/11 (h pairs) ----
    #pragma unroll
    for (int j = 0; j < 4; j++) {
      int h = ln + 32 * j;
      if (h < HIDC) {
        float a0 = 0.0f, a1 = 0.0f;
        #pragma unroll
        for (int b = 0; b < NBC; b++) {
          float w1 = sm->pw.W1[b][h];
          a0 = fmaf(sm->emb[e0][b], w1, a0);
          a1 = fmaf(sm->emb[e1][b], w1, a1);
        }
        sm->X[e0][h >> 1][10 + (h & 1)] = geluf(a0 * 0.31622776601683794f + sm->pw.b1[h]);
        sm->X[e1][h >> 1][10 + (h & 1)] = geluf(a1 * 0.31622776601683794f + sm->pw.b1[h]);
      }
    }
    __syncwarp();

    // ---- stage 1b: pairwise-h matvec (f32x2 over h parity) ----
    u64 AC0[6] = {}, AC1[6] = {};
    if (act) {
      #pragma unroll 2
      for (int h2 = 0; h2 < 50; h2++) {
        u64 H0 = *reinterpret_cast<const u64*>(&sm->X[e0][h2][10]);
        u64 H1 = *reinterpret_cast<const u64*>(&sm->X[e1][h2][10]);
        const __half* wp = &sm->pw.W2i[h2][6 * ln][0];
        #pragma unroll
        for (int j = 0; j < 6; j++) {
          float2 wj = ldh2(wp + 2 * j);
          u64 W = pk(wj.x, wj.y);
          fma2(AC0[j], H0, W);
          fma2(AC1[j], H1, W);
        }
      }
    }
    float wv[2][2][3];
    #pragma unroll
    for (int j = 0; j < 6; j++) {
      float lo, hi;
      upk(lo, hi, AC0[j]); wv[0][j / 3][j % 3] = lo + hi;
      upk(lo, hi, AC1[j]); wv[1][j / 3][j % 3] = lo + hi;
    }

    // ---- stage 2: source matvecs (packed over ch) ----
    u64 H0p = 0ull, H1p = 0ull, SC0p = 0ull, SC1p = 0ull;
    if (act) {
      #pragma unroll 5
      for (int t = 0; t < MULC; t++) {
        float s0 = sm->s[e0][t];
        float s1 = sm->s[e1][t];
        float2 wl = ldh2(&sm->pw.Wl1[t][u0]);
        float2 ws = ldh2(&sm->pw.Wsc[0][t][u0]);
        u64 WL = pk(wl.x, wl.y), WS = pk(ws.x, ws.y);
        u64 S0 = pk(s0, s0), S1 = pk(s1, s1);
        fma2(H0p, S0, WL);
        fma2(SC0p, S0, WS);
        fma2(H1p, S1, WL);
        fma2(SC1p, S1, WS);
      }
    }
    float h0a[2][2], sca[2][2];
    upk(h0a[0][0], h0a[0][1], H0p);
    upk(h0a[1][0], h0a[1][1], H1p);
    upk(sca[0][0], sca[0][1], SC0p);
    upk(sca[1][0], sca[1][1], SC1p);
    __syncwarp();
    if (act) {
      #pragma unroll
      for (int e = 0; e < 2; e++) {
        int le = e0 + e;
        #pragma unroll
        for (int ch = 0; ch < 2; ch++) {
          int u = u0 + ch;
          float h0 = h0a[e][ch] * INVS50;
          float* xr = sm->X[le][u];
          xr[9]  = h0 * wv[e][ch][0] * 0.1f;   // a0
          xr[10] = h0 * wv[e][ch][1] * 0.1f;   // a1
          xr[11] = h0 * wv[e][ch][2] * 0.1f;   // a2
          sm->s[le][u] = siluf(CS * sca[e][ch] * INVS50);
        }
      }
    }
    __syncwarp();

    // ---- stage 3: packed f32x2; pairs (x1,x2)(x3,x0)(x4,x5)(x6,x7)(x8,a0)(a1,a2) ----
    u64 A[2][2][6] = {};
    if (act) {
      #pragma unroll 2
      for (int u = 0; u < MULC; u++) {
        float2 ws0 = ldh2(&sm->pw.Wsc[0][u][u0]);
        float2 ws1 = ldh2(&sm->pw.Wsc[1][u][u0]);
        float2 ws2 = ldh2(&sm->pw.Wsc[2][u][u0]);
        float2 l0 = ldh2(&sm->pw.Wl2[0][u][u0]);
        float2 l1 = ldh2(&sm->pw.Wl2[1][u][u0]);
        float2 l2 = ldh2(&sm->pw.Wl2[2][u][u0]);
        u64 Q0x = pk(ws1.x, ws1.x);
        u64 Q1x = pk(ws1.x, ws0.x);
        u64 Q2x = pk(ws2.x, ws2.x);
        u64 Q3x = pk(ws2.x, l0.x);
        u64 Q4x = pk(l1.x, l2.x);
        u64 Q0y = pk(ws1.y, ws1.y);
        u64 Q1y = pk(ws1.y, ws0.y);
        u64 Q2y = pk(ws2.y, ws2.y);
        u64 Q3y = pk(ws2.y, l0.y);
        u64 Q4y = pk(l1.y, l2.y);
        {
          const ulonglong2* xp = reinterpret_cast<const ulonglong2*>(sm->X[e0][u]);
          ulonglong2 xa = xp[0], xb = xp[1], xc = xp[2];
          fma2(A[0][0][0], xa.x, Q0x);
          fma2(A[0][0][1], xa.y, Q1x);
          fma2(A[0][0][2], xb.x, Q2x);
          fma2(A[0][0][3], xb.y, Q2x);
          fma2(A[0][0][4], xc.x, Q3x);
          fma2(A[0][0][5], xc.y, Q4x);
          fma2(A[0][1][0], xa.x, Q0y);
          fma2(A[0][1][1], xa.y, Q1y);
          fma2(A[0][1][2], xb.x, Q2y);
          fma2(A[0][1][3], xb.y, Q2y);
          fma2(A[0][1][4], xc.x, Q3y);
          fma2(A[0][1][5], xc.y, Q4y);
        }
        {
          const ulonglong2* xp = reinterpret_cast<const ulonglong2*>(sm->X[e1][u]);
          ulonglong2 xa = xp[0], xb = xp[1], xc = xp[2];
          fma2(A[1][0][0], xa.x, Q0x);
          fma2(A[1][0][1], xa.y, Q1x);
          fma2(A[1][0][2], xb.x, Q2x);
          fma2(A[1][0][3], xb.y, Q2x);
          fma2(A[1][0][4], xc.x, Q3x);
          fma2(A[1][0][5], xc.y, Q4x);
          fma2(A[1][1][0], xa.x, Q0y);
          fma2(A[1][1][1], xa.y, Q1y);
          fma2(A[1][1][2], xb.x, Q2y);
          fma2(A[1][1][3], xb.y, Q2y);
          fma2(A[1][1][4], xc.x, Q3y);
          fma2(A[1][1][5], xc.y, Q4y);
        }
      }
    }
    __syncwarp();   // all lanes done reading X
    if (act) {
      #pragma unroll
      for (int e = 0; e < 2; e++) {
        int le = e0 + e;
        const float* shl = sm->shv[le];
        #pragma unroll
        for (int ch = 0; ch < 2; ch++) {
          int u = u0 + ch;
          float ac0, ac1, ac2, ac3, ac4, ac5, ac6, ac7, ac8, b0, b1v, b2;
          upk(ac1, ac2, A[e][ch][0]);
          upk(ac3, ac0, A[e][ch][1]);
          upk(ac4, ac5, A[e][ch][2]);
          upk(ac6, ac7, A[e][ch][3]);
          upk(ac8, b0,  A[e][ch][4]);
          upk(b1v, b2,  A[e][ch][5]);
          float* xr = sm->X[le][u];
          float x0n = CS * INVS50 * ac0 + CXK0 * b0;
          float y1 = CS * INVS50 * ac1 + CXK1 * b1v * shl[1];
          float y2 = CS * INVS50 * ac2 + CXK1 * b1v * shl[2];
          float y3 = CS * INVS50 * ac3 + CXK1 * b1v * shl[3];
          xr[3] = x0n;
          if (i < 2) {
            xr[0] = y1;
            xr[1] = y2;
            xr[2] = y3;
            xr[4] = CS * INVS50 * ac4 + CXK2 * b2 * shl[4];
            xr[5] = CS * INVS50 * ac5 + CXK2 * b2 * shl[5];
            xr[6] = CS * INVS50 * ac6 + CXK2 * b2 * shl[6];
            xr[7] = CS * INVS50 * ac7 + CXK2 * b2 * shl[7];
            xr[8] = CS * INVS50 * ac8 + CXK2 * b2 * shl[8];
          } else {
            xs[e][ch][0] = y1;
            xs[e][ch][1] = y2;
            xs[e][ch][2] = y3;
          }
        }
      }
    }
    __syncwarp();

    // ---- stage 4: gate (packed over ch) ----
    u64 GA0 = 0ull, GA1 = 0ull;
    if (act) {
      #pragma unroll 5
      for (int u = 0; u < MULC; u++) {
        float t0 = sm->X[e0][u][3];   // x0 at phys 3
        float t1 = sm->X[e1][u][3];
        float2 wg = ldh2(&sm->pw.Wg[u][u0]);
        u64 WG = pk(wg.x, wg.y);
        u64 T0 = pk(t0, t0), T1 = pk(t1, t1);
        fma2(GA0, T0, WG);
        fma2(GA1, T1, WG);
      }
    }
    float ga[2][2];
    upk(ga[0][0], ga[0][1], GA0);
    upk(ga[1][0], ga[1][1], GA1);
    __syncwarp();
    if (act) {
      #pragma unroll
      for (int e = 0; e < 2; e++) {
        int le = e0 + e;
        #pragma unroll
        for (int ch = 0; ch < 2; ch++) {
          int u = u0 + ch;
          float g = sigmoidf(ga[e][ch] * INVS50);
          if (i < 2) {
            float* xr = sm->X[le][u];
            float4 Af = *reinterpret_cast<const float4*>(xr);
            float4 Bf = *reinterpret_cast<const float4*>(xr + 4);
            float x8 = xr[8];
            float4 qa = make_float4(Af.x * g, Af.y * g, Af.z * g, siluf(Af.w));
            float4 qb = make_float4(Bf.x * g, Bf.y * g, Bf.z * g, Bf.w * g);
            *reinterpret_cast<float4*>(xr)     = qa;
            *reinterpret_cast<float4*>(xr + 4) = qb;
            xr[8] = x8 * g;
          } else {
            xs[e][ch][0] *= g;
            xs[e][ch][1] *= g;
            xs[e][ch][2] *= g;
          }
        }
      }
    }
    __syncwarp();
  }

  // ---------------- output (from registers) ----------------
  {
    float p[2][3] = {};
    if (act) {
      float wo0 = Wout_g[u0];
      float wo1 = Wout_g[u0 + 1];
      #pragma unroll
      for (int e = 0; e < 2; e++) {
        p[e][0] = xs[e][0][0] * wo0 + xs[e][1][0] * wo1;
        p[e][1] = xs[e][0][1] * wo0 + xs[e][1][1] * wo1;
        p[e][2] = xs[e][0][2] * wo0 + xs[e][1][2] * wo1;
      }
    }
    #pragma unroll
    for (int off = 16; off; off >>= 1) {
      #pragma unroll
      for (int e = 0; e < 2; e++) {
        p[e][0] += __shfl_xor_sync(0xffffffffu, p[e][0], off);
        p[e][1] += __shfl_xor_sync(0xffffffffu, p[e][1], off);
        p[e][2] += __shfl_xor_sync(0xffffffffu, p[e][2], off);
      }
    }
    if (ln == 0) {
      int eg0 = blockIdx.x * TE + e0;
      float* od = out + (size_t)(2 * eg0) * 3;
      od[0] = 0.0f; od[1] = 0.0f; od[2] = 0.0f;
      od[3] = p[0][0] * INVS50;
      od[4] = p[0][1] * INVS50;
      od[5] = p[0][2] * INVS50;
      od[6] = 0.0f; od[7] = 0.0f; od[8] = 0.0f;
      od[9]  = p[1][0] * INVS50;
      od[10] = p[1][1] * INVS50;
      od[11] = p[1][2] * INVS50;
    }
  }
}

extern "C" void kernel_launch(void* const* d_in, const int* in_sizes, int n_in,
                              void* d_out, int out_size) {
  const float* node_pos = (const float*)d_in[0];
  const float* bar_alpha = (const float*)d_in[1];
  const float* W_embed  = (const float*)d_in[2];
  const float* Wsc      = (const float*)d_in[3];
  const float* Wlin1    = (const float*)d_in[4];
  const float* W1       = (const float*)d_in[5];
  const float* b1       = (const float*)d_in[6];
  const float* W2       = (const float*)d_in[7];
  const float* Wlin2    = (const float*)d_in[8];
  const float* Wgate    = (const float*)d_in[9];
  const float* W_out    = (const float*)d_in[10];
  float* out = (float*)d_out;

  pack_kernel<<<3, 256>>>(Wsc, Wlin1, Wlin2, Wgate, W1, b1, W2);

  int E = in_sizes[0] / 6;
  size_t smem = sizeof(SM);
  cudaFuncSetAttribute(slinky_kernel, cudaFuncAttributeMaxDynamicSharedMemorySize, (int)smem);
  slinky_kernel<<<E / TE, NTHREADS, smem>>>(node_pos, bar_alpha, W_embed, W_out, out);
}